// round 14
// baseline (speedup 1.0000x reference)
#include <cuda_runtime.h>
#include <cuda_fp16.h>
#include <mma.h>

using namespace nvcuda;

#define NN   100000
#define NE   1200000
#define DIM  64
#define NL   3
#define NG   256
#define RHID 128
#define ROUT 32

#define SCAN_CHUNK 1024
#define NB_SCAN ((NN + SCAN_CHUNK - 1) / SCAN_CHUNK)   // 98

// Scratch (__device__ globals: allocation-guard safe)
__device__ __half d_hx[NN * DIM];            // fp16 copy of x (12.8 MB)
__device__ __half d_h[NL][NN * DIM];         // 38.4 MB
__device__ float  d_g[NG * NL * DIM];        // 192 KB
__device__ int    d_deg[NN];
__device__ int    d_rowptr[NN];
__device__ int    d_cursor[NN];
__device__ int    d_csrc[NE];
__device__ int    d_blocksum[128];

// ---------------------------------------------------------------------------
// x -> fp16 conversion (once per launch)
// ---------------------------------------------------------------------------
__global__ void convert_x_kernel(const float* __restrict__ x) {
    int i = blockIdx.x * blockDim.x + threadIdx.x;   // one float4 = 4 elems
    if (i < NN * DIM / 4) {
        float4 v = reinterpret_cast<const float4*>(x)[i];
        __half2 lo = __floats2half2_rn(v.x, v.y);
        __half2 hi = __floats2half2_rn(v.z, v.w);
        reinterpret_cast<uint2*>(d_hx)[i] =
            make_uint2(*reinterpret_cast<unsigned*>(&lo), *reinterpret_cast<unsigned*>(&hi));
    }
}

// ---------------------------------------------------------------------------
// CSR build: histogram -> 2-level exclusive scan -> cursor fill
// ---------------------------------------------------------------------------
__global__ void zero_deg_kernel() {
    int i = blockIdx.x * blockDim.x + threadIdx.x;
    if (i < NN) d_deg[i] = 0;
}

__global__ void hist_kernel(const int* __restrict__ dst) {
    int e = blockIdx.x * blockDim.x + threadIdx.x;
    if (e < NE) atomicAdd(&d_deg[dst[e]], 1);
}

__global__ void bsum_kernel() {               // grid = NB_SCAN, 256 thr
    __shared__ int ssum[256];
    int b = blockIdx.x, t = threadIdx.x;
    int base = b * SCAN_CHUNK;
    int s = 0;
    for (int i = t; i < SCAN_CHUNK; i += 256) {
        int idx = base + i;
        if (idx < NN) s += d_deg[idx];
    }
    ssum[t] = s; __syncthreads();
    for (int o = 128; o > 0; o >>= 1) {
        if (t < o) ssum[t] += ssum[t + o];
        __syncthreads();
    }
    if (t == 0) d_blocksum[b] = ssum[0];
}

__global__ void scan_bsums_kernel() {         // 1 block, 128 thr
    __shared__ int sb[128];
    int t = threadIdx.x;
    int v = (t < NB_SCAN) ? d_blocksum[t] : 0;
    sb[t] = v; __syncthreads();
    for (int o = 1; o < 128; o <<= 1) {
        int add = (t >= o) ? sb[t - o] : 0;
        __syncthreads();
        sb[t] += add;
        __syncthreads();
    }
    if (t < NB_SCAN) d_blocksum[t] = sb[t] - v;   // exclusive
}

__global__ void scan_chunks_kernel() {        // grid = NB_SCAN, 256 thr
    __shared__ int tsum[256];
    int b = blockIdx.x, t = threadIdx.x;
    int base = b * SCAN_CHUNK;
    int idx0 = base + t * 4;
    int v[4], s = 0;
#pragma unroll
    for (int j = 0; j < 4; j++) {
        int idx = idx0 + j;
        v[j] = (idx < NN) ? d_deg[idx] : 0;
        s += v[j];
    }
    tsum[t] = s; __syncthreads();
    int mine = s;
    for (int o = 1; o < 256; o <<= 1) {
        int add = (t >= o) ? tsum[t - o] : 0;
        __syncthreads();
        tsum[t] += add;
        __syncthreads();
    }
    int run = tsum[t] - mine + d_blocksum[b];
#pragma unroll
    for (int j = 0; j < 4; j++) {
        int idx = idx0 + j;
        if (idx < NN) { d_rowptr[idx] = run; d_cursor[idx] = run; run += v[j]; }
    }
}

__global__ void fill_kernel(const int* __restrict__ src,
                            const int* __restrict__ dst) {
    int e = blockIdx.x * blockDim.x + threadIdx.x;
    if (e < NE) {
        int p = atomicAdd(&d_cursor[dst[e]], 1);
        d_csrc[p] = src[e];
    }
}

// ---------------------------------------------------------------------------
// Fused GIN layer (fp16 h, fp32 accum gather, tensor-core gemm).
// Phase 1 (gather): 8 warps x 8 nodes; lane owns cols [2l,2l+1] = one __half2.
//   32 lanes x 4B = one 128B fp16 row per warp load. fp32 accum -> fp16 smem.
// Phase 2 (gemm): wmma m16n16k16. W split W_hi + W_lo (both fp16) removes the
//   systematic fp16-W rounding that would NOT cancel in the graph readout:
//   acc = A@W_hi + A@W_lo reconstructs fp32 W to ~1e-7.
//   8 warps x 2 (16x16) tiles x 4 k-steps x {hi,lo}. Epilogue: acc -> smem
//   (reusing the 16KB W region as float[64][64]) -> bias + ReLU -> fp16 h.
// ---------------------------------------------------------------------------
#define INS_PADH 72      // halves per row (144B rows: conflict-free, 32B-aligned tiles)

__global__ void __launch_bounds__(256, 4)
gin_layer_kernel(const float* __restrict__ gW,
                 const float* __restrict__ gB,
                 const float* __restrict__ eps, int layer) {
    __shared__ __align__(16) __half Wsh[2 * DIM * DIM];   // [0]=hi, [1]=lo; 16 KB
    __shared__ __align__(16) __half insh[64 * INS_PADH];  // 9 KB

    const __half* __restrict__ hp = (layer == 0) ? d_hx : d_h[layer - 1];
    int t  = threadIdx.x;
    int n0 = blockIdx.x * 64;
    int warp = t >> 5, lane = t & 31;

    // Stage W as hi/lo fp16 split (16 elems per thread)
    const float* Wg = gW + layer * DIM * DIM;
    for (int i = t; i < DIM * DIM; i += 256) {
        float w = Wg[i];
        __half hi = __float2half_rn(w);
        __half lo = __float2half_rn(w - __half2float(hi));
        Wsh[i] = hi;
        Wsh[DIM * DIM + i] = lo;
    }

    // ---- Phase 1: warp-per-node gather into fp16 smem (fp32 accum) ----
    float e1 = 1.0f + eps[layer];
#pragma unroll
    for (int i = 0; i < 8; i++) {
        int nl = warp * 8 + i;               // local node 0..63
        int n  = n0 + nl;
        float ax = 0.f, ay = 0.f;
        if (n < NN) {
            unsigned own = reinterpret_cast<const unsigned*>(hp + (size_t)n * DIM)[lane];
            {
                float2 f = __half22float2(*reinterpret_cast<__half2*>(&own));
                ax = e1 * f.x; ay = e1 * f.y;
            }
            int beg = d_rowptr[n];
            int deg = d_deg[n];
            int e = 0;
            for (; e + 4 <= deg; e += 4) {
                int s0 = d_csrc[beg + e + 0];
                int s1 = d_csrc[beg + e + 1];
                int s2 = d_csrc[beg + e + 2];
                int s3 = d_csrc[beg + e + 3];
                unsigned v0 = reinterpret_cast<const unsigned*>(hp + (size_t)s0 * DIM)[lane];
                unsigned v1 = reinterpret_cast<const unsigned*>(hp + (size_t)s1 * DIM)[lane];
                unsigned v2 = reinterpret_cast<const unsigned*>(hp + (size_t)s2 * DIM)[lane];
                unsigned v3 = reinterpret_cast<const unsigned*>(hp + (size_t)s3 * DIM)[lane];
                float2 f0 = __half22float2(*reinterpret_cast<__half2*>(&v0));
                float2 f1 = __half22float2(*reinterpret_cast<__half2*>(&v1));
                float2 f2 = __half22float2(*reinterpret_cast<__half2*>(&v2));
                float2 f3 = __half22float2(*reinterpret_cast<__half2*>(&v3));
                ax += (f0.x + f1.x) + (f2.x + f3.x);
                ay += (f0.y + f1.y) + (f2.y + f3.y);
            }
            for (; e < deg; e++) {
                int s = d_csrc[beg + e];
                unsigned v = reinterpret_cast<const unsigned*>(hp + (size_t)s * DIM)[lane];
                float2 f = __half22float2(*reinterpret_cast<__half2*>(&v));
                ax += f.x; ay += f.y;
            }
        }
        *reinterpret_cast<__half2*>(&insh[nl * INS_PADH + 2 * lane]) =
            __floats2half2_rn(ax, ay);
    }
    __syncthreads();

    // ---- Phase 2: wmma gemm. Warp w owns 16x16 tiles w and w+8 of the 4x4 grid ----
    wmma::fragment<wmma::accumulator, 16, 16, 16, float> acc0, acc1;
    wmma::fill_fragment(acc0, 0.0f);
    wmma::fill_fragment(acc1, 0.0f);

    int m0 = (warp >> 2) * 16,       nc0 = (warp & 3) * 16;        // tile w
    int m1 = ((warp + 8) >> 2) * 16, nc1 = ((warp + 8) & 3) * 16;  // tile w+8

#pragma unroll
    for (int k = 0; k < 4; k++) {
        wmma::fragment<wmma::matrix_a, 16, 16, 16, __half, wmma::row_major> afr0, afr1;
        wmma::fragment<wmma::matrix_b, 16, 16, 16, __half, wmma::row_major> bhi, blo;
        wmma::load_matrix_sync(afr0, &insh[m0 * INS_PADH + k * 16], INS_PADH);
        wmma::load_matrix_sync(afr1, &insh[m1 * INS_PADH + k * 16], INS_PADH);

        wmma::load_matrix_sync(bhi, &Wsh[(k * 16) * DIM + nc0], DIM);
        wmma::load_matrix_sync(blo, &Wsh[DIM * DIM + (k * 16) * DIM + nc0], DIM);
        wmma::mma_sync(acc0, afr0, bhi, acc0);
        wmma::mma_sync(acc0, afr0, blo, acc0);

        wmma::load_matrix_sync(bhi, &Wsh[(k * 16) * DIM + nc1], DIM);
        wmma::load_matrix_sync(blo, &Wsh[DIM * DIM + (k * 16) * DIM + nc1], DIM);
        wmma::mma_sync(acc1, afr1, bhi, acc1);
        wmma::mma_sync(acc1, afr1, blo, acc1);
    }
    __syncthreads();   // all Wsh reads done -> safe to reuse as float staging

    float* outs = reinterpret_cast<float*>(Wsh);   // 64x64 fp32 = 16 KB
    wmma::store_matrix_sync(&outs[m0 * DIM + nc0], acc0, DIM, wmma::mem_row_major);
    wmma::store_matrix_sync(&outs[m1 * DIM + nc1], acc1, DIM, wmma::mem_row_major);
    __syncthreads();

    // ---- Epilogue: bias + ReLU -> fp16 global (4 half4-groups per thread) ----
    const float* bias = gB + layer * DIM;
    __half* hl = d_h[layer];
#pragma unroll
    for (int q = 0; q < 4; q++) {
        int i = t + q * 256;                // 0..1023
        int node = i >> 4, c4 = (i & 15) << 2;
        int n = n0 + node;
        if (n < NN) {
            float o0 = fmaxf(outs[node * DIM + c4 + 0] + bias[c4 + 0], 0.f);
            float o1 = fmaxf(outs[node * DIM + c4 + 1] + bias[c4 + 1], 0.f);
            float o2 = fmaxf(outs[node * DIM + c4 + 2] + bias[c4 + 2], 0.f);
            float o3 = fmaxf(outs[node * DIM + c4 + 3] + bias[c4 + 3], 0.f);
            __half2 lo = __floats2half2_rn(o0, o1);
            __half2 hi = __floats2half2_rn(o2, o3);
            reinterpret_cast<uint2*>(hl + (size_t)n * DIM + c4)[0] =
                make_uint2(*reinterpret_cast<unsigned*>(&lo), *reinterpret_cast<unsigned*>(&hi));
        }
    }
}

// ---------------------------------------------------------------------------
// Readout: segmented running sum over sorted graph_ids (fp16 in, fp32 accum).
// ---------------------------------------------------------------------------
__global__ void zero_g_kernel() {             // grid 192, block 256 -> 49152
    int i = blockIdx.x * blockDim.x + threadIdx.x;
    d_g[i] = 0.f;
}

#define RO_CHUNK 128
__global__ void readout_kernel(const int* __restrict__ gid) {
    int t   = threadIdx.x;                    // 0..191
    int lay = t >> 6, col = t & 63;
    int n0  = blockIdx.x * RO_CHUNK;
    int nend = min(n0 + RO_CHUNK, NN);
    const __half* __restrict__ hp = d_h[lay];

    float acc = 0.f;
    int cur = gid[n0];
    for (int n = n0; n < nend; n++) {
        int gi = gid[n];
        if (gi != cur) {
            atomicAdd(&d_g[cur * (NL * DIM) + t], acc);
            acc = 0.f;
            cur = gi;
        }
        acc += __half2float(hp[(size_t)n * DIM + col]);
    }
    atomicAdd(&d_g[cur * (NL * DIM) + t], acc);
}

// ---------------------------------------------------------------------------
// Readout MLP
// ---------------------------------------------------------------------------
__global__ void mlp_kernel(const float* __restrict__ W1, const float* __restrict__ b1,
                           const float* __restrict__ W2, const float* __restrict__ b2,
                           float* __restrict__ out) {
    int b = blockIdx.x, t = threadIdx.x;      // 192 threads
    __shared__ float gv[NL * DIM];
    __shared__ float hid[RHID];

    gv[t] = d_g[b * (NL * DIM) + t];
    __syncthreads();

    if (t < RHID) {
        float acc = b1[t];
#pragma unroll 4
        for (int k = 0; k < NL * DIM; k++)
            acc = fmaf(gv[k], W1[k * RHID + t], acc);
        hid[t] = fmaxf(acc, 0.f);
    }
    __syncthreads();

    if (t < ROUT) {
        float acc = b2[t];
#pragma unroll 4
        for (int k = 0; k < RHID; k++)
            acc = fmaf(hid[k], W2[k * ROUT + t], acc);
        out[b * ROUT + t] = acc;
    }
}

// ---------------------------------------------------------------------------
extern "C" void kernel_launch(void* const* d_in, const int* in_sizes, int n_in,
                              void* d_out, int out_size) {
    const float* x   = (const float*)d_in[0];
    const float* gW  = (const float*)d_in[1];
    const float* gB  = (const float*)d_in[2];
    const float* eps = (const float*)d_in[3];
    const float* rW1 = (const float*)d_in[4];
    const float* rb1 = (const float*)d_in[5];
    const float* rW2 = (const float*)d_in[6];
    const float* rb2 = (const float*)d_in[7];
    const int*   src = (const int*)d_in[8];
    const int*   dst = (const int*)d_in[9];
    const int*   gid = (const int*)d_in[10];
    float* out = (float*)d_out;

    // CSR build + x conversion (once per launch)
    zero_deg_kernel<<<(NN + 255) / 256, 256>>>();
    hist_kernel<<<(NE + 255) / 256, 256>>>(dst);
    convert_x_kernel<<<(NN * DIM / 4 + 255) / 256, 256>>>(x);
    bsum_kernel<<<NB_SCAN, 256>>>();
    scan_bsums_kernel<<<1, 128>>>();
    scan_chunks_kernel<<<NB_SCAN, 256>>>();
    fill_kernel<<<(NE + 255) / 256, 256>>>(src, dst);

    zero_g_kernel<<<192, 256>>>();

    for (int l = 0; l < NL; l++)
        gin_layer_kernel<<<(NN + 63) / 64, 256>>>(gW, gB, eps, l);

    readout_kernel<<<(NN + RO_CHUNK - 1) / RO_CHUNK, 192>>>(gid);
    mlp_kernel<<<NG, 192>>>(rW1, rb1, rW2, rb2, out);
}

// round 15
// speedup vs baseline: 1.0944x; 1.0944x over previous
#include <cuda_runtime.h>
#include <cuda_fp16.h>

#define NN   100000
#define NE   1200000
#define DIM  64
#define NL   3
#define NG   256
#define RHID 128
#define ROUT 32

#define SCAN_CHUNK 1024
#define NB_SCAN ((NN + SCAN_CHUNK - 1) / SCAN_CHUNK)   // 98

// Scratch (__device__ globals: allocation-guard safe)
__device__ __half d_hx[NN * DIM];            // fp16 copy of x (12.8 MB)
__device__ __half d_h[NL][NN * DIM];         // 38.4 MB
__device__ float  d_g[NG * NL * DIM];        // 192 KB
__device__ int    d_deg[NN];
__device__ int    d_rowptr[NN];
__device__ int    d_cursor[NN];
__device__ int    d_csrc[NE];
__device__ int    d_blocksum[128];

// ---------------------------------------------------------------------------
// x -> fp16 conversion (once per launch)
// ---------------------------------------------------------------------------
__global__ void convert_x_kernel(const float* __restrict__ x) {
    int i = blockIdx.x * blockDim.x + threadIdx.x;   // one float4 = 4 elems
    if (i < NN * DIM / 4) {
        float4 v = reinterpret_cast<const float4*>(x)[i];
        __half2 lo = __floats2half2_rn(v.x, v.y);
        __half2 hi = __floats2half2_rn(v.z, v.w);
        reinterpret_cast<uint2*>(d_hx)[i] =
            make_uint2(*reinterpret_cast<unsigned*>(&lo), *reinterpret_cast<unsigned*>(&hi));
    }
}

// ---------------------------------------------------------------------------
// Zero deg + g in one launch
// ---------------------------------------------------------------------------
__global__ void zero_misc_kernel() {
    int i = blockIdx.x * blockDim.x + threadIdx.x;
    if (i < NN) d_deg[i] = 0;
    if (i < NG * NL * DIM) d_g[i] = 0.f;
}

// ---------------------------------------------------------------------------
// CSR build: histogram -> 2-level exclusive scan -> cursor fill
// ---------------------------------------------------------------------------
__global__ void hist_kernel(const int* __restrict__ dst) {
    int e = blockIdx.x * blockDim.x + threadIdx.x;
    if (e < NE) atomicAdd(&d_deg[dst[e]], 1);
}

__global__ void bsum_kernel() {               // grid = NB_SCAN, 256 thr
    __shared__ int ssum[256];
    int b = blockIdx.x, t = threadIdx.x;
    int base = b * SCAN_CHUNK;
    int s = 0;
    for (int i = t; i < SCAN_CHUNK; i += 256) {
        int idx = base + i;
        if (idx < NN) s += d_deg[idx];
    }
    ssum[t] = s; __syncthreads();
    for (int o = 128; o > 0; o >>= 1) {
        if (t < o) ssum[t] += ssum[t + o];
        __syncthreads();
    }
    if (t == 0) d_blocksum[b] = ssum[0];
}

__global__ void scan_bsums_kernel() {         // 1 block, 128 thr
    __shared__ int sb[128];
    int t = threadIdx.x;
    int v = (t < NB_SCAN) ? d_blocksum[t] : 0;
    sb[t] = v; __syncthreads();
    for (int o = 1; o < 128; o <<= 1) {
        int add = (t >= o) ? sb[t - o] : 0;
        __syncthreads();
        sb[t] += add;
        __syncthreads();
    }
    if (t < NB_SCAN) d_blocksum[t] = sb[t] - v;   // exclusive
}

__global__ void scan_chunks_kernel() {        // grid = NB_SCAN, 256 thr
    __shared__ int tsum[256];
    int b = blockIdx.x, t = threadIdx.x;
    int base = b * SCAN_CHUNK;
    int idx0 = base + t * 4;
    int v[4], s = 0;
#pragma unroll
    for (int j = 0; j < 4; j++) {
        int idx = idx0 + j;
        v[j] = (idx < NN) ? d_deg[idx] : 0;
        s += v[j];
    }
    tsum[t] = s; __syncthreads();
    int mine = s;
    for (int o = 1; o < 256; o <<= 1) {
        int add = (t >= o) ? tsum[t - o] : 0;
        __syncthreads();
        tsum[t] += add;
        __syncthreads();
    }
    int run = tsum[t] - mine + d_blocksum[b];
#pragma unroll
    for (int j = 0; j < 4; j++) {
        int idx = idx0 + j;
        if (idx < NN) { d_rowptr[idx] = run; d_cursor[idx] = run; run += v[j]; }
    }
}

__global__ void fill_kernel(const int* __restrict__ src,
                            const int* __restrict__ dst) {
    int e = blockIdx.x * blockDim.x + threadIdx.x;
    if (e < NE) {
        int p = atomicAdd(&d_cursor[dst[e]], 1);
        d_csrc[p] = src[e];
    }
}

// ---------------------------------------------------------------------------
// Fused GIN layer (fp16 h storage, fp32 accum, FFMA 4x4 micro-tile gemm).
// Phase 1 (gather): 8 warps x 8 nodes; lane owns cols [2l,2l+1] (one __half2).
//   Neighbor indices are fetched 32-at-a-time with ONE coalesced load
//   (csrc[beg+lane]) and broadcast via shfl -> the per-iteration
//   index->row dependent chain is gone; row loads issue unroll-8 ->
//   8 independent 128B loads in flight per warp.
// Phase 2: the R13-winning register-blocked 4x4 FFMA micro-tile.
// ---------------------------------------------------------------------------
#define INS_PAD 68

__global__ void __launch_bounds__(256, 4)
gin_layer_kernel(const float* __restrict__ gW,
                 const float* __restrict__ gB,
                 const float* __restrict__ eps, int layer) {
    __shared__ float Ws[DIM * DIM];          // 16 KB
    __shared__ float ins[64 * INS_PAD];      // 17.4 KB

    const __half* __restrict__ hp = (layer == 0) ? d_hx : d_h[layer - 1];
    int t  = threadIdx.x;
    int n0 = blockIdx.x * 64;
    int warp = t >> 5, lane = t & 31;

    // Stage W (vectorized)
    const float4* Wg = reinterpret_cast<const float4*>(gW + layer * DIM * DIM);
    float4* Wsv = reinterpret_cast<float4*>(Ws);
    for (int i = t; i < DIM * DIM / 4; i += 256) Wsv[i] = Wg[i];

    // ---- Phase 1: warp-per-node gather, shfl-cached indices ----
    float e1 = 1.0f + eps[layer];
#pragma unroll
    for (int i = 0; i < 8; i++) {
        int nl = warp * 8 + i;               // local node 0..63
        int n  = n0 + nl;
        float ax = 0.f, ay = 0.f;
        if (n < NN) {                        // warp-uniform branch
            unsigned own = reinterpret_cast<const unsigned*>(hp + (size_t)n * DIM)[lane];
            {
                float2 f = __half22float2(*reinterpret_cast<__half2*>(&own));
                ax = e1 * f.x; ay = e1 * f.y;
            }
            int beg = d_rowptr[n];
            int deg = d_deg[n];
            for (int chunk = 0; chunk < deg; chunk += 32) {
                int cnt = deg - chunk; if (cnt > 32) cnt = 32;
                int myidx = (lane < cnt) ? d_csrc[beg + chunk + lane] : 0;
                int e = 0;
                for (; e + 8 <= cnt; e += 8) {
                    unsigned v[8];
#pragma unroll
                    for (int j = 0; j < 8; j++) {
                        int s = __shfl_sync(0xffffffffu, myidx, e + j);
                        v[j] = reinterpret_cast<const unsigned*>(hp + (size_t)s * DIM)[lane];
                    }
#pragma unroll
                    for (int j = 0; j < 8; j++) {
                        float2 f = __half22float2(*reinterpret_cast<__half2*>(&v[j]));
                        ax += f.x; ay += f.y;
                    }
                }
                for (; e + 4 <= cnt; e += 4) {
                    unsigned v[4];
#pragma unroll
                    for (int j = 0; j < 4; j++) {
                        int s = __shfl_sync(0xffffffffu, myidx, e + j);
                        v[j] = reinterpret_cast<const unsigned*>(hp + (size_t)s * DIM)[lane];
                    }
#pragma unroll
                    for (int j = 0; j < 4; j++) {
                        float2 f = __half22float2(*reinterpret_cast<__half2*>(&v[j]));
                        ax += f.x; ay += f.y;
                    }
                }
                for (; e < cnt; e++) {
                    int s = __shfl_sync(0xffffffffu, myidx, e);
                    unsigned v = reinterpret_cast<const unsigned*>(hp + (size_t)s * DIM)[lane];
                    float2 f = __half22float2(*reinterpret_cast<__half2*>(&v));
                    ax += f.x; ay += f.y;
                }
            }
        }
        *reinterpret_cast<float2*>(&ins[nl * INS_PAD + 2 * lane]) = make_float2(ax, ay);
    }
    __syncthreads();

    // ---- Phase 2: 4x4 register-blocked gemm + bias + ReLU -> fp16 ----
    int tx = t & 15;          // cols 4tx..4tx+3
    int ty = t >> 4;          // nodes 4ty..4ty+3

    const float* b4 = gB + layer * DIM + 4 * tx;
    float4 acc0 = make_float4(b4[0], b4[1], b4[2], b4[3]);
    float4 acc1 = acc0, acc2 = acc0, acc3 = acc0;

    const float* ir0 = &ins[(4 * ty + 0) * INS_PAD];
    const float* ir1 = &ins[(4 * ty + 1) * INS_PAD];
    const float* ir2 = &ins[(4 * ty + 2) * INS_PAD];
    const float* ir3 = &ins[(4 * ty + 3) * INS_PAD];

#pragma unroll 8
    for (int k = 0; k < DIM; k++) {
        float4 w = *reinterpret_cast<const float4*>(&Ws[k * DIM + 4 * tx]);
        float a0 = ir0[k], a1 = ir1[k], a2 = ir2[k], a3 = ir3[k];
        acc0.x = fmaf(a0, w.x, acc0.x); acc0.y = fmaf(a0, w.y, acc0.y);
        acc0.z = fmaf(a0, w.z, acc0.z); acc0.w = fmaf(a0, w.w, acc0.w);
        acc1.x = fmaf(a1, w.x, acc1.x); acc1.y = fmaf(a1, w.y, acc1.y);
        acc1.z = fmaf(a1, w.z, acc1.z); acc1.w = fmaf(a1, w.w, acc1.w);
        acc2.x = fmaf(a2, w.x, acc2.x); acc2.y = fmaf(a2, w.y, acc2.y);
        acc2.z = fmaf(a2, w.z, acc2.z); acc2.w = fmaf(a2, w.w, acc2.w);
        acc3.x = fmaf(a3, w.x, acc3.x); acc3.y = fmaf(a3, w.y, acc3.y);
        acc3.z = fmaf(a3, w.z, acc3.z); acc3.w = fmaf(a3, w.w, acc3.w);
    }

    __half* hl = d_h[layer];
#pragma unroll
    for (int i = 0; i < 4; i++) {
        int n = n0 + 4 * ty + i;
        if (n < NN) {
            float4 a = (i == 0) ? acc0 : (i == 1) ? acc1 : (i == 2) ? acc2 : acc3;
            __half2 lo = __floats2half2_rn(fmaxf(a.x, 0.f), fmaxf(a.y, 0.f));
            __half2 hi = __floats2half2_rn(fmaxf(a.z, 0.f), fmaxf(a.w, 0.f));
            reinterpret_cast<uint2*>(hl + (size_t)n * DIM + 4 * tx)[0] =
                make_uint2(*reinterpret_cast<unsigned*>(&lo), *reinterpret_cast<unsigned*>(&hi));
        }
    }
}

// ---------------------------------------------------------------------------
// Readout: segmented running sum over sorted graph_ids (fp16 in, fp32 accum).
// ---------------------------------------------------------------------------
#define RO_CHUNK 128
__global__ void readout_kernel(const int* __restrict__ gid) {
    int t   = threadIdx.x;                    // 0..191
    int lay = t >> 6, col = t & 63;
    int n0  = blockIdx.x * RO_CHUNK;
    int nend = min(n0 + RO_CHUNK, NN);
    const __half* __restrict__ hp = d_h[lay];

    float acc = 0.f;
    int cur = gid[n0];
    for (int n = n0; n < nend; n++) {
        int gi = gid[n];
        if (gi != cur) {
            atomicAdd(&d_g[cur * (NL * DIM) + t], acc);
            acc = 0.f;
            cur = gi;
        }
        acc += __half2float(hp[(size_t)n * DIM + col]);
    }
    atomicAdd(&d_g[cur * (NL * DIM) + t], acc);
}

// ---------------------------------------------------------------------------
// Readout MLP
// ---------------------------------------------------------------------------
__global__ void mlp_kernel(const float* __restrict__ W1, const float* __restrict__ b1,
                           const float* __restrict__ W2, const float* __restrict__ b2,
                           float* __restrict__ out) {
    int b = blockIdx.x, t = threadIdx.x;      // 192 threads
    __shared__ float gv[NL * DIM];
    __shared__ float hid[RHID];

    gv[t] = d_g[b * (NL * DIM) + t];
    __syncthreads();

    if (t < RHID) {
        float acc = b1[t];
#pragma unroll 4
        for (int k = 0; k < NL * DIM; k++)
            acc = fmaf(gv[k], W1[k * RHID + t], acc);
        hid[t] = fmaxf(acc, 0.f);
    }
    __syncthreads();

    if (t < ROUT) {
        float acc = b2[t];
#pragma unroll 4
        for (int k = 0; k < RHID; k++)
            acc = fmaf(hid[k], W2[k * ROUT + t], acc);
        out[b * ROUT + t] = acc;
    }
}

// ---------------------------------------------------------------------------
extern "C" void kernel_launch(void* const* d_in, const int* in_sizes, int n_in,
                              void* d_out, int out_size) {
    const float* x   = (const float*)d_in[0];
    const float* gW  = (const float*)d_in[1];
    const float* gB  = (const float*)d_in[2];
    const float* eps = (const float*)d_in[3];
    const float* rW1 = (const float*)d_in[4];
    const float* rb1 = (const float*)d_in[5];
    const float* rW2 = (const float*)d_in[6];
    const float* rb2 = (const float*)d_in[7];
    const int*   src = (const int*)d_in[8];
    const int*   dst = (const int*)d_in[9];
    const int*   gid = (const int*)d_in[10];
    float* out = (float*)d_out;

    // CSR build + x conversion (once per launch)
    zero_misc_kernel<<<(NN + 255) / 256, 256>>>();
    hist_kernel<<<(NE + 255) / 256, 256>>>(dst);
    convert_x_kernel<<<(NN * DIM / 4 + 255) / 256, 256>>>(x);
    bsum_kernel<<<NB_SCAN, 256>>>();
    scan_bsums_kernel<<<1, 128>>>();
    scan_chunks_kernel<<<NB_SCAN, 256>>>();
    fill_kernel<<<(NE + 255) / 256, 256>>>(src, dst);

    for (int l = 0; l < NL; l++)
        gin_layer_kernel<<<(NN + 63) / 64, 256>>>(gW, gB, eps, l);

    readout_kernel<<<(NN + RO_CHUNK - 1) / RO_CHUNK, 192>>>(gid);
    mlp_kernel<<<NG, 192>>>(rW1, rb1, rW2, rb2, out);
}

// round 16
// speedup vs baseline: 1.0957x; 1.0012x over previous
#include <cuda_runtime.h>
#include <cuda_fp16.h>

#define NN   100000
#define NE   1200000
#define DIM  64
#define NL   3
#define NG   256
#define RHID 128
#define ROUT 32

#define SCAN_CHUNK 1024
#define NB_SCAN ((NN + SCAN_CHUNK - 1) / SCAN_CHUNK)   // 98

#define NTILES ((NN + 63) / 64)       // 1563
#define PGRID  592                    // 148 SMs x 4 blocks

// Scratch (__device__ globals: allocation-guard safe)
__device__ __half d_hx[NN * DIM];            // fp16 copy of x (12.8 MB)
__device__ __half d_h[NL][NN * DIM];         // 38.4 MB
__device__ float  d_g[NG * NL * DIM];        // 192 KB
__device__ int    d_deg[NN];
__device__ int    d_rowptr[NN];
__device__ int    d_cursor[NN];
__device__ int    d_csrc[NE];
__device__ int    d_blocksum[128];

// ---------------------------------------------------------------------------
// x -> fp16 conversion (once per launch)
// ---------------------------------------------------------------------------
__global__ void convert_x_kernel(const float* __restrict__ x) {
    int i = blockIdx.x * blockDim.x + threadIdx.x;   // one float4 = 4 elems
    if (i < NN * DIM / 4) {
        float4 v = reinterpret_cast<const float4*>(x)[i];
        __half2 lo = __floats2half2_rn(v.x, v.y);
        __half2 hi = __floats2half2_rn(v.z, v.w);
        reinterpret_cast<uint2*>(d_hx)[i] =
            make_uint2(*reinterpret_cast<unsigned*>(&lo), *reinterpret_cast<unsigned*>(&hi));
    }
}

// ---------------------------------------------------------------------------
// Zero deg + g in one launch
// ---------------------------------------------------------------------------
__global__ void zero_misc_kernel() {
    int i = blockIdx.x * blockDim.x + threadIdx.x;
    if (i < NN) d_deg[i] = 0;
    if (i < NG * NL * DIM) d_g[i] = 0.f;
}

// ---------------------------------------------------------------------------
// CSR build: histogram -> 2-level exclusive scan -> cursor fill
// ---------------------------------------------------------------------------
__global__ void hist_kernel(const int* __restrict__ dst) {
    int e = blockIdx.x * blockDim.x + threadIdx.x;
    if (e < NE) atomicAdd(&d_deg[dst[e]], 1);
}

__global__ void bsum_kernel() {               // grid = NB_SCAN, 256 thr
    __shared__ int ssum[256];
    int b = blockIdx.x, t = threadIdx.x;
    int base = b * SCAN_CHUNK;
    int s = 0;
    for (int i = t; i < SCAN_CHUNK; i += 256) {
        int idx = base + i;
        if (idx < NN) s += d_deg[idx];
    }
    ssum[t] = s; __syncthreads();
    for (int o = 128; o > 0; o >>= 1) {
        if (t < o) ssum[t] += ssum[t + o];
        __syncthreads();
    }
    if (t == 0) d_blocksum[b] = ssum[0];
}

__global__ void scan_bsums_kernel() {         // 1 block, 128 thr
    __shared__ int sb[128];
    int t = threadIdx.x;
    int v = (t < NB_SCAN) ? d_blocksum[t] : 0;
    sb[t] = v; __syncthreads();
    for (int o = 1; o < 128; o <<= 1) {
        int add = (t >= o) ? sb[t - o] : 0;
        __syncthreads();
        sb[t] += add;
        __syncthreads();
    }
    if (t < NB_SCAN) d_blocksum[t] = sb[t] - v;   // exclusive
}

__global__ void scan_chunks_kernel() {        // grid = NB_SCAN, 256 thr
    __shared__ int tsum[256];
    int b = blockIdx.x, t = threadIdx.x;
    int base = b * SCAN_CHUNK;
    int idx0 = base + t * 4;
    int v[4], s = 0;
#pragma unroll
    for (int j = 0; j < 4; j++) {
        int idx = idx0 + j;
        v[j] = (idx < NN) ? d_deg[idx] : 0;
        s += v[j];
    }
    tsum[t] = s; __syncthreads();
    int mine = s;
    for (int o = 1; o < 256; o <<= 1) {
        int add = (t >= o) ? tsum[t - o] : 0;
        __syncthreads();
        tsum[t] += add;
        __syncthreads();
    }
    int run = tsum[t] - mine + d_blocksum[b];
#pragma unroll
    for (int j = 0; j < 4; j++) {
        int idx = idx0 + j;
        if (idx < NN) { d_rowptr[idx] = run; d_cursor[idx] = run; run += v[j]; }
    }
}

__global__ void fill_kernel(const int* __restrict__ src,
                            const int* __restrict__ dst) {
    int e = blockIdx.x * blockDim.x + threadIdx.x;
    if (e < NE) {
        int p = atomicAdd(&d_cursor[dst[e]], 1);
        d_csrc[p] = src[e];
    }
}

// ---------------------------------------------------------------------------
// Fused GIN layer: persistent blocks + paired-neighbor gather + FFMA gemm.
// Grid = 592 (148x4); each block strides over 64-node tiles (no wave tail;
// W staged ONCE per block).
// Gather: warp per node. Lane (h = lane>>4, q = lane&15) owns cols 4q..4q+3
//   (uint2 = 8B); half-warp h loads neighbor e+h -> ONE LDG.64 instruction
//   covers TWO neighbors (halves row-load issue count). fp32 accumulators,
//   halves combined via shfl_xor(16). Indices chunk-loaded + shfl-broadcast.
// Gemm: R13-winning register-blocked 4x4 FFMA micro-tile.
// ---------------------------------------------------------------------------
#define INS_PAD 68

__global__ void __launch_bounds__(256, 4)
gin_layer_kernel(const float* __restrict__ gW,
                 const float* __restrict__ gB,
                 const float* __restrict__ eps, int layer) {
    __shared__ float Ws[DIM * DIM];          // 16 KB
    __shared__ float ins[64 * INS_PAD];      // 17.4 KB

    const __half* __restrict__ hp = (layer == 0) ? d_hx : d_h[layer - 1];
    int t    = threadIdx.x;
    int warp = t >> 5, lane = t & 31;
    int h    = lane >> 4;                    // half-warp id (neighbor parity)
    int q    = lane & 15;                    // col quad: cols 4q..4q+3

    // Stage W once per block
    const float4* Wg = reinterpret_cast<const float4*>(gW + layer * DIM * DIM);
    float4* Wsv = reinterpret_cast<float4*>(Ws);
    for (int i = t; i < DIM * DIM / 4; i += 256) Wsv[i] = Wg[i];

    float e1 = 1.0f + eps[layer];
    int tx = t & 15;          // gemm: cols 4tx..4tx+3
    int ty = t >> 4;          // gemm: nodes 4ty..4ty+3
    const float* b4 = gB + layer * DIM + 4 * tx;
    float bx = b4[0], by = b4[1], bz = b4[2], bw = b4[3];
    __half* hl = d_h[layer];

    for (int tile = blockIdx.x; tile < NTILES; tile += PGRID) {
        int n0 = tile * 64;
        __syncthreads();                     // ins safe to overwrite

        // ---- Phase 1: gather (warp per node, paired neighbor loads) ----
#pragma unroll
        for (int i = 0; i < 8; i++) {
            int nl = warp * 8 + i;           // local node 0..63
            int n  = n0 + nl;
            float a0 = 0.f, a1 = 0.f, a2 = 0.f, a3 = 0.f;
            if (n < NN) {                    // warp-uniform
                // own row (both halves load same 128B -> broadcast; half 1 zeroed)
                uint2 own = *reinterpret_cast<const uint2*>(hp + (size_t)n * DIM + 4 * q);
                {
                    float2 f0 = __half22float2(*reinterpret_cast<__half2*>(&own.x));
                    float2 f1 = __half22float2(*reinterpret_cast<__half2*>(&own.y));
                    float sc = (h == 0) ? e1 : 0.f;
                    a0 = sc * f0.x; a1 = sc * f0.y; a2 = sc * f1.x; a3 = sc * f1.y;
                }
                int beg = d_rowptr[n];
                int deg = d_deg[n];
                for (int chunk = 0; chunk < deg; chunk += 32) {
                    int cnt = deg - chunk; if (cnt > 32) cnt = 32;
                    int myidx = (lane < cnt) ? d_csrc[beg + chunk + lane] : 0;
                    int e = 0;
                    for (; e + 8 <= cnt; e += 8) {     // 8 neighbors = 4 paired loads
                        uint2 v[4];
#pragma unroll
                        for (int j = 0; j < 4; j++) {
                            int s = __shfl_sync(0xffffffffu, myidx, e + 2 * j + h);
                            v[j] = *reinterpret_cast<const uint2*>(hp + (size_t)s * DIM + 4 * q);
                        }
#pragma unroll
                        for (int j = 0; j < 4; j++) {
                            float2 f0 = __half22float2(*reinterpret_cast<__half2*>(&v[j].x));
                            float2 f1 = __half22float2(*reinterpret_cast<__half2*>(&v[j].y));
                            a0 += f0.x; a1 += f0.y; a2 += f1.x; a3 += f1.y;
                        }
                    }
                    for (; e < cnt; e += 2) {          // remainder, paired
                        int ei = e + h;
                        int s = __shfl_sync(0xffffffffu, myidx, (ei < cnt) ? ei : e);
                        if (ei < cnt) {
                            uint2 v = *reinterpret_cast<const uint2*>(hp + (size_t)s * DIM + 4 * q);
                            float2 f0 = __half22float2(*reinterpret_cast<__half2*>(&v.x));
                            float2 f1 = __half22float2(*reinterpret_cast<__half2*>(&v.y));
                            a0 += f0.x; a1 += f0.y; a2 += f1.x; a3 += f1.y;
                        }
                    }
                }
                // combine the two halves
                a0 += __shfl_xor_sync(0xffffffffu, a0, 16);
                a1 += __shfl_xor_sync(0xffffffffu, a1, 16);
                a2 += __shfl_xor_sync(0xffffffffu, a2, 16);
                a3 += __shfl_xor_sync(0xffffffffu, a3, 16);
            }
            if (h == 0)
                *reinterpret_cast<float4*>(&ins[nl * INS_PAD + 4 * q]) =
                    make_float4(a0, a1, a2, a3);
        }
        __syncthreads();

        // ---- Phase 2: 4x4 register-blocked gemm + bias + ReLU -> fp16 ----
        float4 acc0 = make_float4(bx, by, bz, bw);
        float4 acc1 = acc0, acc2 = acc0, acc3 = acc0;

        const float* ir0 = &ins[(4 * ty + 0) * INS_PAD];
        const float* ir1 = &ins[(4 * ty + 1) * INS_PAD];
        const float* ir2 = &ins[(4 * ty + 2) * INS_PAD];
        const float* ir3 = &ins[(4 * ty + 3) * INS_PAD];

#pragma unroll 8
        for (int k = 0; k < DIM; k++) {
            float4 w = *reinterpret_cast<const float4*>(&Ws[k * DIM + 4 * tx]);
            float a0 = ir0[k], a1 = ir1[k], a2 = ir2[k], a3 = ir3[k];
            acc0.x = fmaf(a0, w.x, acc0.x); acc0.y = fmaf(a0, w.y, acc0.y);
            acc0.z = fmaf(a0, w.z, acc0.z); acc0.w = fmaf(a0, w.w, acc0.w);
            acc1.x = fmaf(a1, w.x, acc1.x); acc1.y = fmaf(a1, w.y, acc1.y);
            acc1.z = fmaf(a1, w.z, acc1.z); acc1.w = fmaf(a1, w.w, acc1.w);
            acc2.x = fmaf(a2, w.x, acc2.x); acc2.y = fmaf(a2, w.y, acc2.y);
            acc2.z = fmaf(a2, w.z, acc2.z); acc2.w = fmaf(a2, w.w, acc2.w);
            acc3.x = fmaf(a3, w.x, acc3.x); acc3.y = fmaf(a3, w.y, acc3.y);
            acc3.z = fmaf(a3, w.z, acc3.z); acc3.w = fmaf(a3, w.w, acc3.w);
        }

#pragma unroll
        for (int i = 0; i < 4; i++) {
            int n = n0 + 4 * ty + i;
            if (n < NN) {
                float4 a = (i == 0) ? acc0 : (i == 1) ? acc1 : (i == 2) ? acc2 : acc3;
                __half2 lo = __floats2half2_rn(fmaxf(a.x, 0.f), fmaxf(a.y, 0.f));
                __half2 hi = __floats2half2_rn(fmaxf(a.z, 0.f), fmaxf(a.w, 0.f));
                reinterpret_cast<uint2*>(hl + (size_t)n * DIM + 4 * tx)[0] =
                    make_uint2(*reinterpret_cast<unsigned*>(&lo), *reinterpret_cast<unsigned*>(&hi));
            }
        }
    }
}

// ---------------------------------------------------------------------------
// Readout: segmented running sum over sorted graph_ids (fp16 in, fp32 accum).
// ---------------------------------------------------------------------------
#define RO_CHUNK 128
__global__ void readout_kernel(const int* __restrict__ gid) {
    int t   = threadIdx.x;                    // 0..191
    int lay = t >> 6, col = t & 63;
    int n0  = blockIdx.x * RO_CHUNK;
    int nend = min(n0 + RO_CHUNK, NN);
    const __half* __restrict__ hp = d_h[lay];

    float acc = 0.f;
    int cur = gid[n0];
    for (int n = n0; n < nend; n++) {
        int gi = gid[n];
        if (gi != cur) {
            atomicAdd(&d_g[cur * (NL * DIM) + t], acc);
            acc = 0.f;
            cur = gi;
        }
        acc += __half2float(hp[(size_t)n * DIM + col]);
    }
    atomicAdd(&d_g[cur * (NL * DIM) + t], acc);
}

// ---------------------------------------------------------------------------
// Readout MLP
// ---------------------------------------------------------------------------
__global__ void mlp_kernel(const float* __restrict__ W1, const float* __restrict__ b1,
                           const float* __restrict__ W2, const float* __restrict__ b2,
                           float* __restrict__ out) {
    int b = blockIdx.x, t = threadIdx.x;      // 192 threads
    __shared__ float gv[NL * DIM];
    __shared__ float hid[RHID];

    gv[t] = d_g[b * (NL * DIM) + t];
    __syncthreads();

    if (t < RHID) {
        float acc = b1[t];
#pragma unroll 4
        for (int k = 0; k < NL * DIM; k++)
            acc = fmaf(gv[k], W1[k * RHID + t], acc);
        hid[t] = fmaxf(acc, 0.f);
    }
    __syncthreads();

    if (t < ROUT) {
        float acc = b2[t];
#pragma unroll 4
        for (int k = 0; k < RHID; k++)
            acc = fmaf(hid[k], W2[k * ROUT + t], acc);
        out[b * ROUT + t] = acc;
    }
}

// ---------------------------------------------------------------------------
extern "C" void kernel_launch(void* const* d_in, const int* in_sizes, int n_in,
                              void* d_out, int out_size) {
    const float* x   = (const float*)d_in[0];
    const float* gW  = (const float*)d_in[1];
    const float* gB  = (const float*)d_in[2];
    const float* eps = (const float*)d_in[3];
    const float* rW1 = (const float*)d_in[4];
    const float* rb1 = (const float*)d_in[5];
    const float* rW2 = (const float*)d_in[6];
    const float* rb2 = (const float*)d_in[7];
    const int*   src = (const int*)d_in[8];
    const int*   dst = (const int*)d_in[9];
    const int*   gid = (const int*)d_in[10];
    float* out = (float*)d_out;

    // CSR build + x conversion (once per launch)
    zero_misc_kernel<<<(NN + 255) / 256, 256>>>();
    hist_kernel<<<(NE + 255) / 256, 256>>>(dst);
    convert_x_kernel<<<(NN * DIM / 4 + 255) / 256, 256>>>(x);
    bsum_kernel<<<NB_SCAN, 256>>>();
    scan_bsums_kernel<<<1, 128>>>();
    scan_chunks_kernel<<<NB_SCAN, 256>>>();
    fill_kernel<<<(NE + 255) / 256, 256>>>(src, dst);

    for (int l = 0; l < NL; l++)
        gin_layer_kernel<<<PGRID, 256>>>(gW, gB, eps, l);

    readout_kernel<<<(NN + RO_CHUNK - 1) / RO_CHUNK, 192>>>(gid);
    mlp_kernel<<<NG, 192>>>(rW1, rb1, rW2, rb2, out);
}